// round 2
// baseline (speedup 1.0000x reference)
#include <cuda_runtime.h>
#include <cstdint>
#include <cstddef>

// Problem constants (static per the reference setup_inputs).
#define NAG 64           // B*A = 2*32
#define DDIM 360         // K * 2 * fut_len = 6*60
#define DD (DDIM*DDIM)   // 129600
#define MODE_LEN 60      // 2*fut_len

// ---------------- scratch (sanctioned __device__ globals) ----------------
__device__ float g_S [(size_t)NAG*DD];
__device__ float g_X0[(size_t)NAG*DD];
__device__ float g_X1[(size_t)NAG*DD];
__device__ float g_Y [(size_t)NAG*DD];
__device__ float g_r[NAG];
__device__ float g_c[NAG];
__device__ int   g_upd[NAG];      // selected & initialized  -> Kalman update
__device__ int   g_initnew[NAG];  // selected & ~initialized -> init branch
__device__ int   g_initout[NAG];  // initialized | selected

__device__ __forceinline__ float* bufsel(int s) {
    switch (s) {
        case 0:  return g_S;
        case 1:  return g_X0;
        case 2:  return g_X1;
        default: return g_Y;
    }
}

// shift map: row i of A has its single 1 at column src(i)
__device__ __forceinline__ int srcIdx(int g) {
    int l = g % MODE_LEN;
    return (l < MODE_LEN - 2) ? (g + 2) : g;
}

// ---------------- flag dtype sniffing ----------------
// Returns 0 = uint8 bool, 1 = int32 0/1, 2 = float32 0.0/1.0
// Reads only the first 64 bytes (safe for all three layouts: uint8 buffer is
// exactly 64B; int32/f32 buffers are 256B).
__device__ int detect_mode(const unsigned char* p) {
    int n_off = 0, n_3f = 0;
    for (int t = 0; t < 64; t++) {
        unsigned char b = p[t];
        if ((t & 3) && b) n_off++;
        if (((t & 3) == 3) && b == 0x3F) n_3f++;
    }
    if (n_off == 0) return 1;   // only 4-byte-aligned bytes nonzero -> int32
    if (n_3f > 0)  return 2;    // IEEE754 1.0f exponent bytes present -> float32
    return 0;                   // generic small nonzero bytes everywhere -> uint8
}

__device__ __forceinline__ bool read_flag(const void* p, int t, int mode) {
    if (mode == 1) return ((const int*)p)[t] != 0;
    if (mode == 2) return ((const float*)p)[t] != 0.0f;
    return ((const unsigned char*)p)[t] != 0;
}

// ---------------- tiny per-agent flag/scalar prep ----------------
__global__ void prep_flags(const float* __restrict__ rs,
                           const void* __restrict__ ini,
                           const void* __restrict__ sel) {
    __shared__ int mode_i, mode_s;
    if (threadIdx.x == 0) {
        mode_i = detect_mode((const unsigned char*)ini);
        mode_s = detect_mode((const unsigned char*)sel);
    }
    __syncthreads();
    int t = threadIdx.x;
    if (t >= NAG) return;
    float r = rs[t] + 1.0f;          // OBSERVATION_INIT = 1
    bool i8 = read_flag(ini, t, mode_i);
    bool s8 = read_flag(sel, t, mode_s);
    g_r[t] = r;
    g_upd[t] = (s8 && i8);
    g_initnew[t] = (s8 && !i8);
    g_initout[t] = (s8 || i8);
}

// ---------------- build S = A P A^T + (1 + r) I ----------------
__global__ void build_S(const float* __restrict__ cov) {
    int a = blockIdx.y;
    if (!g_upd[a]) return;
    int e = blockIdx.x * blockDim.x + threadIdx.x;
    if (e >= DD) return;
    int i = e / DDIM, j = e % DDIM;
    float v = cov[(size_t)a * DD + (size_t)srcIdx(i) * DDIM + srcIdx(j)];
    if (i == j) v += 1.0f + g_r[a];
    g_S[(size_t)a * DD + e] = v;
}

// ---------------- Gershgorin bound -> Newton scale c ----------------
__global__ void gersh(void) {
    int a = blockIdx.x;
    if (!g_upd[a]) return;
    const float* S = g_S + (size_t)a * DD;
    int warp = threadIdx.x >> 5, lane = threadIdx.x & 31;
    float m = 0.0f;
    for (int i = warp; i < DDIM; i += 8) {
        float s = 0.0f;
        const float* row = S + (size_t)i * DDIM;
        for (int j = lane; j < DDIM; j += 32) s += fabsf(row[j]);
        #pragma unroll
        for (int o = 16; o; o >>= 1) s += __shfl_xor_sync(0xffffffffu, s, o);
        m = fmaxf(m, s);
    }
    __shared__ float wm[8];
    if (lane == 0) wm[warp] = m;
    __syncthreads();
    if (threadIdx.x == 0) {
        float G = 0.0f;
        #pragma unroll
        for (int w = 0; w < 8; w++) G = fmaxf(G, wm[w]);
        float r = g_r[a];
        float lmin = 1.0f + r;           // rigorous: P_pred >= I
        g_c[a] = 2.0f / (lmin + G);
    }
}

// ---------------- X0 = 2c I - c^2 S  (closed-form first Newton step) ----
__global__ void fill_X(void) {
    int a = blockIdx.y;
    if (!g_upd[a]) return;
    int e = blockIdx.x * blockDim.x + threadIdx.x;
    if (e >= DD) return;
    int i = e / DDIM, j = e % DDIM;
    float c = g_c[a];
    float s = g_S[(size_t)a * DD + e];
    g_X0[(size_t)a * DD + e] = ((i == j) ? 2.0f * c : 0.0f) - c * c * s;
}

// ---------------- batched 360x360x360 fp32 GEMM -------------------------
// MODE 0: C = A*B
// MODE 1: C = 2*X - A*B   (X indexed like C; used as Xnew = 2X - X*Y)
#define BM 64
#define BN 64
#define BK 16
#define PADA 68

template<int MODE>
__global__ __launch_bounds__(256, 4)
void gemm_k(int sA, int sB, int sX, int sC) {
    int z = blockIdx.z;
    if (!g_upd[z]) return;
    const float* A = bufsel(sA) + (size_t)z * DD;
    const float* B = bufsel(sB) + (size_t)z * DD;
    const float* X = bufsel(sX) + (size_t)z * DD;
    float*       C = bufsel(sC) + (size_t)z * DD;

    __shared__ float As[BK][PADA];
    __shared__ float Bs[BK][BN];

    int m0 = blockIdx.x * BM, n0 = blockIdx.y * BN;
    int tid = threadIdx.x;
    int tm = tid & 15, tn = tid >> 4;        // 16x16 thread tile, 4x4 per thread

    int la_k = tid & 15;     // A load: k within tile
    int la_m = tid >> 4;     // A load: m base (0..15)
    int lb_n = tid & 63;     // B load: n within tile
    int lb_k = tid >> 6;     // B load: k base (0..3)

    float acc[4][4] = {};

    for (int k0 = 0; k0 < DDIM; k0 += BK) {
        #pragma unroll
        for (int u = 0; u < 4; u++) {
            int mm = la_m + 16 * u;
            int gm = m0 + mm, gk = k0 + la_k;
            float v = (gm < DDIM && gk < DDIM) ? A[(size_t)gm * DDIM + gk] : 0.0f;
            As[la_k][mm] = v;
        }
        #pragma unroll
        for (int u = 0; u < 4; u++) {
            int kk = lb_k + 4 * u;
            int gk = k0 + kk, gn = n0 + lb_n;
            float v = (gk < DDIM && gn < DDIM) ? B[(size_t)gk * DDIM + gn] : 0.0f;
            Bs[kk][lb_n] = v;
        }
        __syncthreads();
        #pragma unroll
        for (int kk = 0; kk < BK; kk++) {
            float a0 = As[kk][tm * 4 + 0];
            float a1 = As[kk][tm * 4 + 1];
            float a2 = As[kk][tm * 4 + 2];
            float a3 = As[kk][tm * 4 + 3];
            float b0 = Bs[kk][tn * 4 + 0];
            float b1 = Bs[kk][tn * 4 + 1];
            float b2 = Bs[kk][tn * 4 + 2];
            float b3 = Bs[kk][tn * 4 + 3];
            acc[0][0] += a0 * b0; acc[0][1] += a0 * b1; acc[0][2] += a0 * b2; acc[0][3] += a0 * b3;
            acc[1][0] += a1 * b0; acc[1][1] += a1 * b1; acc[1][2] += a1 * b2; acc[1][3] += a1 * b3;
            acc[2][0] += a2 * b0; acc[2][1] += a2 * b1; acc[2][2] += a2 * b2; acc[2][3] += a2 * b3;
            acc[3][0] += a3 * b0; acc[3][1] += a3 * b1; acc[3][2] += a3 * b2; acc[3][3] += a3 * b3;
        }
        __syncthreads();
    }

    #pragma unroll
    for (int i = 0; i < 4; i++) {
        int gm = m0 + tm * 4 + i;
        if (gm >= DDIM) continue;
        #pragma unroll
        for (int j = 0; j < 4; j++) {
            int gn = n0 + tn * 4 + j;
            if (gn >= DDIM) continue;
            float o = acc[i][j];
            if (MODE == 1) o = 2.0f * X[(size_t)gm * DDIM + gn] - o;
            C[(size_t)gm * DDIM + gn] = o;
        }
    }
}

// ---------------- outputs ----------------
// out layout (f32): [mean 64*360][cov 64*360*360][initialized 64]
#define OUT_MEAN 0
#define OUT_COV  (NAG * DDIM)
#define OUT_INIT (NAG * DDIM + NAG * DD)

__global__ void finalize_cov(const float* __restrict__ cov,
                             float* __restrict__ out, int sinv_sel) {
    int a = blockIdx.y;
    int e = blockIdx.x * blockDim.x + threadIdx.x;
    if (e >= DD) return;
    int i = e / DDIM, j = e % DDIM;
    float r = g_r[a];
    float o;
    if (g_initnew[a]) {
        o = cov[(size_t)a * DD + e] + ((i == j) ? r : 0.0f);
    } else if (g_upd[a]) {
        const float* Xi = bufsel(sinv_sel) + (size_t)a * DD;
        o = ((i == j) ? r : 0.0f) - r * r * Xi[e];
    } else {
        o = cov[(size_t)a * DD + e];
    }
    out[OUT_COV + (size_t)a * DD + e] = o;
}

__global__ void finalize_mean(const float* __restrict__ mean_in,
                              const float* __restrict__ obs,
                              float* __restrict__ out, int sinv_sel) {
    int a = blockIdx.x;
    int tid = threadIdx.x;
    __shared__ float v[DDIM];

    if (tid == 0) out[OUT_INIT + a] = g_initout[a] ? 1.0f : 0.0f;

    const float* m = mean_in + (size_t)a * DDIM;
    const float* o = obs + (size_t)a * DDIM;
    float* om = out + OUT_MEAN + (size_t)a * DDIM;

    if (g_initnew[a]) {
        for (int i = tid; i < DDIM; i += blockDim.x) om[i] = o[i];
    } else if (g_upd[a]) {
        float r = g_r[a];
        const float* Si = bufsel(sinv_sel) + (size_t)a * DD;
        for (int j = tid; j < DDIM; j += blockDim.x) v[j] = o[j] - m[srcIdx(j)];
        __syncthreads();
        int warp = tid >> 5, lane = tid & 31;
        for (int i = warp; i < DDIM; i += 8) {
            float s = 0.0f;
            const float* row = Si + (size_t)i * DDIM;
            for (int j = lane; j < DDIM; j += 32) s += row[j] * v[j];
            #pragma unroll
            for (int off = 16; off; off >>= 1) s += __shfl_xor_sync(0xffffffffu, s, off);
            if (lane == 0) om[i] = o[i] - r * s;
        }
    } else {
        for (int i = tid; i < DDIM; i += blockDim.x) om[i] = m[i];
    }
}

// ---------------- launch ----------------
extern "C" void kernel_launch(void* const* d_in, const int* in_sizes, int n_in,
                              void* d_out, int out_size) {
    const float* mean = (const float*)d_in[0];
    const float* cov  = (const float*)d_in[1];
    const float* obs  = (const float*)d_in[2];
    const float* rs   = (const float*)d_in[3];
    const void*  ini  = d_in[4];
    const void*  sel  = d_in[5];
    float* out = (float*)d_out;

    const int EB = (DD + 255) / 256;   // 507 blocks over one matrix

    prep_flags<<<1, 64>>>(rs, ini, sel);
    build_S<<<dim3(EB, NAG), 256>>>(cov);
    gersh<<<NAG, 256>>>();
    fill_X<<<dim3(EB, NAG), 256>>>();

    dim3 ggrid((DDIM + BM - 1) / BM, (DDIM + BN - 1) / BN, NAG);  // 6x6x64
    int cur = 1;  // X lives in g_X0
    for (int it = 0; it < 5; it++) {
        gemm_k<0><<<ggrid, 256>>>(0, cur, 0, 3);        // Y = S * X
        int nxt = (cur == 1) ? 2 : 1;
        gemm_k<1><<<ggrid, 256>>>(cur, 3, cur, nxt);    // Xn = 2X - X*Y
        cur = nxt;
    }

    finalize_cov<<<dim3(EB, NAG), 256>>>(cov, out, cur);
    finalize_mean<<<NAG, 256>>>(mean, obs, out, cur);
}

// round 4
// speedup vs baseline: 3.5511x; 3.5511x over previous
#include <cuda_runtime.h>
#include <cuda_bf16.h>
#include <cstdint>
#include <cstddef>

// ---------------- problem constants ----------------
#define NAG 64           // B*A
#define DIN 360          // logical dim
#define DD  (DIN*DIN)
#define MODE_LEN 60
#define DP  384          // padded dim (3 x 128)
#define DP2 (DP*DP)

// ---------------- scratch ----------------
__device__ float g_S [(size_t)NAG*DP2];
__device__ float g_X0[(size_t)NAG*DP2];
__device__ float g_X1[(size_t)NAG*DP2];
__device__ float g_Y [(size_t)NAG*DP2];
__device__ float g_r[NAG];
__device__ float g_c[NAG];
__device__ int   g_upd[NAG];
__device__ int   g_initnew[NAG];
__device__ int   g_initout[NAG];

__device__ __forceinline__ float* bufsel(int s) {
    switch (s) {
        case 0:  return g_S;
        case 1:  return g_X0;
        case 2:  return g_X1;
        default: return g_Y;
    }
}

__device__ __forceinline__ int srcIdx(int g) {
    int l = g % MODE_LEN;
    return (l < MODE_LEN - 2) ? (g + 2) : g;
}

// ---------------- flag dtype sniffing (validated round 2) ----------------
__device__ int detect_mode(const unsigned char* p) {
    int n_off = 0, n_3f = 0;
    for (int t = 0; t < 64; t++) {
        unsigned char b = p[t];
        if ((t & 3) && b) n_off++;
        if (((t & 3) == 3) && b == 0x3F) n_3f++;
    }
    if (n_off == 0) return 1;
    if (n_3f > 0)  return 2;
    return 0;
}
__device__ __forceinline__ bool read_flag(const void* p, int t, int mode) {
    if (mode == 1) return ((const int*)p)[t] != 0;
    if (mode == 2) return ((const float*)p)[t] != 0.0f;
    return ((const unsigned char*)p)[t] != 0;
}

__global__ void prep_flags(const float* __restrict__ rs,
                           const void* __restrict__ ini,
                           const void* __restrict__ sel) {
    __shared__ int mode_i, mode_s;
    if (threadIdx.x == 0) {
        mode_i = detect_mode((const unsigned char*)ini);
        mode_s = detect_mode((const unsigned char*)sel);
    }
    __syncthreads();
    int t = threadIdx.x;
    if (t >= NAG) return;
    float r = rs[t] + 1.0f;
    bool i8 = read_flag(ini, t, mode_i);
    bool s8 = read_flag(sel, t, mode_s);
    g_r[t] = r;
    g_upd[t] = (s8 && i8);
    g_initnew[t] = (s8 && !i8);
    g_initout[t] = (s8 || i8);
}

// ---------------- S = A P A^T + (1+r) I, identity-padded to 384 ---------
__global__ void build_S(const float* __restrict__ cov) {
    int a = blockIdx.y;
    if (!g_upd[a]) return;
    int e = blockIdx.x * blockDim.x + threadIdx.x;
    if (e >= DP2) return;
    int i = e / DP, j = e % DP;
    float v;
    if (i < DIN && j < DIN) {
        v = cov[(size_t)a * DD + (size_t)srcIdx(i) * DIN + srcIdx(j)];
        if (i == j) v += 1.0f + g_r[a];
    } else {
        v = (i == j) ? 1.0f : 0.0f;
    }
    g_S[(size_t)a * DP2 + e] = v;
}

__global__ void gersh(void) {
    int a = blockIdx.x;
    if (!g_upd[a]) return;
    const float* S = g_S + (size_t)a * DP2;
    int warp = threadIdx.x >> 5, lane = threadIdx.x & 31;
    float m = 0.0f;
    for (int i = warp; i < DIN; i += 8) {
        float s = 0.0f;
        const float* row = S + (size_t)i * DP;
        for (int j = lane; j < DIN; j += 32) s += fabsf(row[j]);
        #pragma unroll
        for (int o = 16; o; o >>= 1) s += __shfl_xor_sync(0xffffffffu, s, o);
        m = fmaxf(m, s);
    }
    __shared__ float wm[8];
    if (lane == 0) wm[warp] = m;
    __syncthreads();
    if (threadIdx.x == 0) {
        float G = 0.0f;
        #pragma unroll
        for (int w = 0; w < 8; w++) G = fmaxf(G, wm[w]);
        float lmin = 1.0f + g_r[a];
        g_c[a] = 2.0f / (lmin + G);
    }
}

// X0 = 2c I - c^2 S  (pad region consistent: S=I there)
__global__ void fill_X(void) {
    int a = blockIdx.y;
    if (!g_upd[a]) return;
    int e = blockIdx.x * blockDim.x + threadIdx.x;
    if (e >= DP2) return;
    int i = e / DP, j = e % DP;
    float c = g_c[a];
    float s = g_S[(size_t)a * DP2 + e];
    g_X0[(size_t)a * DP2 + e] = ((i == j) ? 2.0f * c : 0.0f) - c * c * s;
}

// ================= mma.sync bf16 batched GEMM =================
// CTA tile 128x128, 256 threads = 8 warps in 2(m) x 4(n), warp tile 64x32.
// k-chunk 64. All operands symmetric, so C = A*B is computed as an NT GEMM
// (both staged k-major, B via its own rows).
#define LDT 72     // padded SMEM row (bf16 elems): 144B, conflict-free ldmatrix
#define TILE_E (128 * LDT)

__device__ __forceinline__ uint32_t smem_u32(const void* p) {
    uint32_t a;
    asm("{ .reg .u64 t; cvta.to.shared.u64 t, %1; cvt.u32.u64 %0, t; }"
        : "=r"(a) : "l"(p));
    return a;
}

__device__ __forceinline__ uint32_t pack_bf2(float x, float y) {
    __nv_bfloat162 t = __floats2bfloat162_rn(x, y);
    return *reinterpret_cast<uint32_t*>(&t);
}

__device__ __forceinline__ void ldm_x4(uint32_t* r, uint32_t addr) {
    asm volatile("ldmatrix.sync.aligned.m8n8.x4.shared.b16 {%0,%1,%2,%3}, [%4];"
                 : "=r"(r[0]), "=r"(r[1]), "=r"(r[2]), "=r"(r[3]) : "r"(addr));
}

__device__ __forceinline__ void mma_bf16(float* d, const uint32_t* a, const uint32_t* b) {
    asm volatile(
        "mma.sync.aligned.m16n8k16.row.col.f32.bf16.bf16.f32 "
        "{%0,%1,%2,%3}, {%4,%5,%6,%7}, {%8,%9}, {%0,%1,%2,%3};"
        : "+f"(d[0]), "+f"(d[1]), "+f"(d[2]), "+f"(d[3])
        : "r"(a[0]), "r"(a[1]), "r"(a[2]), "r"(a[3]), "r"(b[0]), "r"(b[1]));
}

// SPLIT=0: plain bf16 (hi only). SPLIT=1: hi*hi + hi*lo + lo*hi.
// MODE=0: C = A*B.  MODE=1: C = 2X - A*B.
template<int SPLIT, int MODE>
__global__ __launch_bounds__(256)
void gemm_mma(int sA, int sB, int sX, int sC) {
    int z = blockIdx.z;
    if (!g_upd[z]) return;
    const float* Ap = bufsel(sA) + (size_t)z * DP2;
    const float* Bp = bufsel(sB) + (size_t)z * DP2;
    const float* Xp = bufsel(sX) + (size_t)z * DP2;
    float*       Cp = bufsel(sC) + (size_t)z * DP2;

    extern __shared__ __align__(16) __nv_bfloat16 sm[];
    __nv_bfloat16* Ah = sm;
    __nv_bfloat16* Bh = sm + TILE_E;
    __nv_bfloat16* Al = sm + 2 * TILE_E;  // split only
    __nv_bfloat16* Bl = sm + 3 * TILE_E;

    int tid = threadIdx.x, wid = tid >> 5, lane = tid & 31;
    int wm = (wid & 1) * 64, wn = (wid >> 1) * 32;
    int m0 = blockIdx.x * 128, n0 = blockIdx.y * 128;

    float acc[4][4][4];
    #pragma unroll
    for (int i = 0; i < 4; i++)
        #pragma unroll
        for (int j = 0; j < 4; j++)
            #pragma unroll
            for (int q = 0; q < 4; q++) acc[i][j][q] = 0.0f;

    // ldmatrix lane addressing (within a 128xLDT tile)
    int lt = lane >> 3, lr = lane & 7;
    // A/x4: matrices (m0-7,k0-7),(m8-15,k0-7),(m0-7,k8-15),(m8-15,k8-15)
    int a_row = (lt & 1) * 8 + lr;
    int a_col = (lt >> 1) * 8;
    // B/x4 over two n-tiles: (n0-7,k0-7),(n0-7,k8-15),(n8-15,k0-7),(n8-15,k8-15)
    int b_row = (lt >> 1) * 8 + lr;
    int b_col = (lt & 1) * 8;

    for (int kc = 0; kc < 6; kc++) {
        int k0 = kc * 64;
        // ---- stage fp32 -> bf16 hi (and lo) ----
        #pragma unroll
        for (int it = 0; it < 8; it++) {
            int e = it * 256 + tid;
            int row = e >> 4, qc = (e & 15) * 4;
            float4 va = *(const float4*)(Ap + (size_t)(m0 + row) * DP + k0 + qc);
            float4 vb = *(const float4*)(Bp + (size_t)(n0 + row) * DP + k0 + qc);
            uint2 ha = make_uint2(pack_bf2(va.x, va.y), pack_bf2(va.z, va.w));
            uint2 hb = make_uint2(pack_bf2(vb.x, vb.y), pack_bf2(vb.z, vb.w));
            *(uint2*)&Ah[row * LDT + qc] = ha;
            *(uint2*)&Bh[row * LDT + qc] = hb;
            if (SPLIT) {
                float la0 = va.x - __bfloat162float(__float2bfloat16_rn(va.x));
                float la1 = va.y - __bfloat162float(__float2bfloat16_rn(va.y));
                float la2 = va.z - __bfloat162float(__float2bfloat16_rn(va.z));
                float la3 = va.w - __bfloat162float(__float2bfloat16_rn(va.w));
                float lb0 = vb.x - __bfloat162float(__float2bfloat16_rn(vb.x));
                float lb1 = vb.y - __bfloat162float(__float2bfloat16_rn(vb.y));
                float lb2 = vb.z - __bfloat162float(__float2bfloat16_rn(vb.z));
                float lb3 = vb.w - __bfloat162float(__float2bfloat16_rn(vb.w));
                *(uint2*)&Al[row * LDT + qc] = make_uint2(pack_bf2(la0, la1), pack_bf2(la2, la3));
                *(uint2*)&Bl[row * LDT + qc] = make_uint2(pack_bf2(lb0, lb1), pack_bf2(lb2, lb3));
            }
        }
        __syncthreads();

        // ---- compute 4 k16 steps ----
        #pragma unroll
        for (int ks = 0; ks < 4; ks++) {
            int kk = ks * 16;
            uint32_t afh[4][4], bfh[4][2];
            #pragma unroll
            for (int mt = 0; mt < 4; mt++) {
                uint32_t addr = smem_u32(&Ah[(wm + mt * 16 + a_row) * LDT + kk + a_col]);
                ldm_x4(afh[mt], addr);
            }
            #pragma unroll
            for (int np = 0; np < 2; np++) {
                uint32_t r[4];
                uint32_t addr = smem_u32(&Bh[(wn + np * 16 + b_row) * LDT + kk + b_col]);
                ldm_x4(r, addr);
                bfh[np * 2][0] = r[0]; bfh[np * 2][1] = r[1];
                bfh[np * 2 + 1][0] = r[2]; bfh[np * 2 + 1][1] = r[3];
            }
            #pragma unroll
            for (int mt = 0; mt < 4; mt++)
                #pragma unroll
                for (int nt = 0; nt < 4; nt++)
                    mma_bf16(acc[mt][nt], afh[mt], bfh[nt]);

            if (SPLIT) {
                uint32_t afl[4][4], bfl[4][2];
                #pragma unroll
                for (int mt = 0; mt < 4; mt++) {
                    uint32_t addr = smem_u32(&Al[(wm + mt * 16 + a_row) * LDT + kk + a_col]);
                    ldm_x4(afl[mt], addr);
                }
                #pragma unroll
                for (int np = 0; np < 2; np++) {
                    uint32_t r[4];
                    uint32_t addr = smem_u32(&Bl[(wn + np * 16 + b_row) * LDT + kk + b_col]);
                    ldm_x4(r, addr);
                    bfl[np * 2][0] = r[0]; bfl[np * 2][1] = r[1];
                    bfl[np * 2 + 1][0] = r[2]; bfl[np * 2 + 1][1] = r[3];
                }
                #pragma unroll
                for (int mt = 0; mt < 4; mt++)
                    #pragma unroll
                    for (int nt = 0; nt < 4; nt++) {
                        mma_bf16(acc[mt][nt], afh[mt], bfl[nt]);   // hi*lo
                        mma_bf16(acc[mt][nt], afl[mt], bfh[nt]);   // lo*hi
                    }
            }
        }
        __syncthreads();
    }

    // ---- epilogue: regs -> global ----
    #pragma unroll
    for (int mt = 0; mt < 4; mt++) {
        int r0 = m0 + wm + mt * 16 + (lane >> 2);
        #pragma unroll
        for (int nt = 0; nt < 4; nt++) {
            int c = n0 + wn + nt * 8 + 2 * (lane & 3);
            size_t g0 = (size_t)r0 * DP + c;
            size_t g1 = g0 + 8 * DP;
            float2 v0 = make_float2(acc[mt][nt][0], acc[mt][nt][1]);
            float2 v1 = make_float2(acc[mt][nt][2], acc[mt][nt][3]);
            if (MODE == 1) {
                float2 x0 = *(const float2*)(Xp + g0);
                float2 x1 = *(const float2*)(Xp + g1);
                v0.x = 2.0f * x0.x - v0.x; v0.y = 2.0f * x0.y - v0.y;
                v1.x = 2.0f * x1.x - v1.x; v1.y = 2.0f * x1.y - v1.y;
            }
            *(float2*)(Cp + g0) = v0;
            *(float2*)(Cp + g1) = v1;
        }
    }
}

// ---------------- outputs ----------------
#define OUT_MEAN 0
#define OUT_COV  (NAG * DIN)
#define OUT_INIT (NAG * DIN + NAG * DD)

__global__ void finalize_cov(const float* __restrict__ cov,
                             float* __restrict__ out, int sinv_sel) {
    int a = blockIdx.y;
    int e4 = blockIdx.x * blockDim.x + threadIdx.x;
    if (e4 >= DD / 4) return;
    int i = e4 / 90;
    int jj = (e4 % 90) * 4;
    float r = g_r[a];
    float4 o;
    if (g_initnew[a]) {
        o = *(const float4*)(cov + (size_t)a * DD + (size_t)i * DIN + jj);
        if (i >= jj && i < jj + 4) (&o.x)[i - jj] += r;
    } else if (g_upd[a]) {
        const float* Xi = bufsel(sinv_sel) + (size_t)a * DP2;
        float4 x = *(const float4*)(Xi + (size_t)i * DP + jj);
        float rr = -r * r;
        o.x = rr * x.x; o.y = rr * x.y; o.z = rr * x.z; o.w = rr * x.w;
        if (i >= jj && i < jj + 4) (&o.x)[i - jj] += r;
    } else {
        o = *(const float4*)(cov + (size_t)a * DD + (size_t)i * DIN + jj);
    }
    *(float4*)(out + OUT_COV + (size_t)a * DD + (size_t)i * DIN + jj) = o;
}

__global__ void finalize_mean(const float* __restrict__ mean_in,
                              const float* __restrict__ obs,
                              float* __restrict__ out, int sinv_sel) {
    int a = blockIdx.x;
    int tid = threadIdx.x;
    __shared__ float v[DIN];

    if (tid == 0) out[OUT_INIT + a] = g_initout[a] ? 1.0f : 0.0f;

    const float* m = mean_in + (size_t)a * DIN;
    const float* o = obs + (size_t)a * DIN;
    float* om = out + OUT_MEAN + (size_t)a * DIN;

    if (g_initnew[a]) {
        for (int i = tid; i < DIN; i += blockDim.x) om[i] = o[i];
    } else if (g_upd[a]) {
        float r = g_r[a];
        const float* Si = bufsel(sinv_sel) + (size_t)a * DP2;
        for (int j = tid; j < DIN; j += blockDim.x) v[j] = o[j] - m[srcIdx(j)];
        __syncthreads();
        int warp = tid >> 5, lane = tid & 31;
        for (int i = warp; i < DIN; i += 8) {
            float s = 0.0f;
            const float* row = Si + (size_t)i * DP;
            for (int j = lane; j < DIN; j += 32) s += row[j] * v[j];
            #pragma unroll
            for (int off = 16; off; off >>= 1) s += __shfl_xor_sync(0xffffffffu, s, off);
            if (lane == 0) om[i] = o[i] - r * s;
        }
    } else {
        for (int i = tid; i < DIN; i += blockDim.x) om[i] = m[i];
    }
}

// ---------------- launch ----------------
extern "C" void kernel_launch(void* const* d_in, const int* in_sizes, int n_in,
                              void* d_out, int out_size) {
    const float* mean = (const float*)d_in[0];
    const float* cov  = (const float*)d_in[1];
    const float* obs  = (const float*)d_in[2];
    const float* rs   = (const float*)d_in[3];
    const void*  ini  = d_in[4];
    const void*  sel  = d_in[5];
    float* out = (float*)d_out;

    const int SM_PLAIN = 2 * TILE_E * 2;   // 2 tiles * bf16
    const int SM_SPLIT = 4 * TILE_E * 2;   // 4 tiles * bf16

    cudaFuncSetAttribute(gemm_mma<0, 0>, cudaFuncAttributeMaxDynamicSharedMemorySize, SM_PLAIN);
    cudaFuncSetAttribute(gemm_mma<0, 1>, cudaFuncAttributeMaxDynamicSharedMemorySize, SM_PLAIN);
    cudaFuncSetAttribute(gemm_mma<1, 0>, cudaFuncAttributeMaxDynamicSharedMemorySize, SM_SPLIT);
    cudaFuncSetAttribute(gemm_mma<1, 1>, cudaFuncAttributeMaxDynamicSharedMemorySize, SM_SPLIT);

    const int EBP = (DP2 + 255) / 256;

    prep_flags<<<1, 64>>>(rs, ini, sel);
    build_S<<<dim3(EBP, NAG), 256>>>(cov);
    gersh<<<NAG, 256>>>();
    fill_X<<<dim3(EBP, NAG), 256>>>();

    dim3 g3(3, 3, NAG);
    int cur = 1;  // X in g_X0
    // 2 plain bf16 Newton iterations (reach the bf16 floor)
    for (int it = 0; it < 2; it++) {
        gemm_mma<0, 0><<<g3, 256, SM_PLAIN>>>(0, cur, 0, 3);       // Y = S*X
        int nxt = (cur == 1) ? 2 : 1;
        gemm_mma<0, 1><<<g3, 256, SM_PLAIN>>>(cur, 3, cur, nxt);   // Xn = 2X - X*Y
        cur = nxt;
    }
    // 2 split-bf16 iterations (square the floor away)
    for (int it = 0; it < 2; it++) {
        gemm_mma<1, 0><<<g3, 256, SM_SPLIT>>>(0, cur, 0, 3);
        int nxt = (cur == 1) ? 2 : 1;
        gemm_mma<1, 1><<<g3, 256, SM_SPLIT>>>(cur, 3, cur, nxt);
        cur = nxt;
    }

    finalize_cov<<<dim3((DD / 4 + 255) / 256, NAG), 256>>>(cov, out, cur);
    finalize_mean<<<NAG, 256>>>(mean, obs, out, cur);
}